// round 14
// baseline (speedup 1.0000x reference)
#include <cuda_runtime.h>
#include <cuda_bf16.h>
#include <math.h>
#include <cstdint>

#define SEQ 2048
#define DM  2048
#define NH  16
#define DQK 128
#define DV  128
#define NCAT 6144   // q|k|v concatenated head-columns

// ---------------- helpers ----------------------------------------------------
__device__ __forceinline__ uint32_t smem_u32(const void* p) {
    uint32_t a;
    asm("{ .reg .u64 t; cvta.to.shared.u64 t, %1; cvt.u32.u64 %0, t; }"
        : "=r"(a) : "l"(p));
    return a;
}

#define CP_ASYNC16(dst, src) \
    asm volatile("cp.async.cg.shared.global [%0], [%1], 16;" :: "r"(dst), "l"(src))
#define CP_COMMIT() asm volatile("cp.async.commit_group;" ::: "memory")
#define CP_WAIT(n)  asm volatile("cp.async.wait_group %0;" :: "n"(n) : "memory")

__device__ __forceinline__ void ldsm4(uint32_t* r, uint32_t addr) {
    asm volatile("ldmatrix.sync.aligned.m8n8.x4.shared.b16 {%0,%1,%2,%3}, [%4];"
                 : "=r"(r[0]), "=r"(r[1]), "=r"(r[2]), "=r"(r[3]) : "r"(addr));
}
__device__ __forceinline__ void ldsm4t(uint32_t* r, uint32_t addr) {
    asm volatile("ldmatrix.sync.aligned.m8n8.x4.trans.shared.b16 {%0,%1,%2,%3}, [%4];"
                 : "=r"(r[0]), "=r"(r[1]), "=r"(r[2]), "=r"(r[3]) : "r"(addr));
}

__device__ __forceinline__ void mma_bf16(float* d, const uint32_t* a,
                                         uint32_t b0, uint32_t b1) {
    asm volatile(
        "mma.sync.aligned.m16n8k16.row.col.f32.bf16.bf16.f32 "
        "{%0,%1,%2,%3}, {%4,%5,%6,%7}, {%8,%9}, {%0,%1,%2,%3};"
        : "+f"(d[0]), "+f"(d[1]), "+f"(d[2]), "+f"(d[3])
        : "r"(a[0]), "r"(a[1]), "r"(a[2]), "r"(a[3]), "r"(b0), "r"(b1));
}

__device__ __forceinline__ uint32_t pack_bf16x2(float lo, float hi) {
    uint32_t d;
    asm("cvt.rn.bf16x2.f32 %0, %1, %2;" : "=r"(d) : "f"(hi), "f"(lo));
    return d;
}

// ---------------- scratch (device globals) ----------------------------------
__device__ __align__(256) __nv_bfloat16 g_xs[2ull * SEQ * DM];    // 16 MB
__device__ __align__(256) __nv_bfloat16 g_wt[2ull * NCAT * DM];   // 50 MB
__device__ __align__(256) __nv_bfloat16 g_ot[2ull * DM * DM];     // 16 MB
__device__ __align__(256) __nv_bfloat16 g_ys[2ull * SEQ * DM];    // 16 MB
__device__ __align__(256) __nv_bfloat16 g_qs2[2ull * NH * SEQ * DQK];  // 16 MB
__device__ __align__(256) __nv_bfloat16 g_ks2[2ull * NH * SEQ * DQK];  // 16 MB
__device__ __align__(256) __nv_bfloat16 g_vs2[2ull * NH * SEQ * DV];   // 16 MB
__device__ float g_sin[SEQ * 64];
__device__ float g_cos[SEQ * 64];

// ---------------- bf16x2 split ----------------------------------------------
__device__ __forceinline__ void split2(float x, __nv_bfloat16& b0, __nv_bfloat16& b1) {
    b0 = __float2bfloat16(x);
    float r = x - __bfloat162float(b0);
    b1 = __float2bfloat16(r);
}

// ---------------- RoPE sin/cos table ----------------------------------------
__global__ void rope_table_kernel(const float* __restrict__ theta_p) {
    int idx = blockIdx.x * blockDim.x + threadIdx.x;
    if (idx >= SEQ * 64) return;
    int j = idx & 63;
    int s = idx >> 6;
    float theta = *theta_p;
    float rate = theta * (-(float)j / 64.0f);
    float rot  = (float)s * rate;
    double rd = (double)rot;
    g_sin[idx] = (float)sin(rd);
    g_cos[idx] = (float)cos(rd);
}

// ---------------- split x (bf16x2 packed stores) -----------------------------
__global__ void split_x_kernel(const float* __restrict__ x) {
    int i = (blockIdx.x * blockDim.x + threadIdx.x) * 2;
    const size_t N = (size_t)SEQ * DM;
    float2 xv = *(const float2*)&x[i];
    __nv_bfloat16 a0, a1, c0, c1;
    split2(xv.x, a0, a1);
    split2(xv.y, c0, c1);
    __nv_bfloat162 hi; hi.x = a0; hi.y = c0;
    __nv_bfloat162 lo; lo.x = a1; lo.y = c1;
    *(__nv_bfloat162*)&g_xs[i] = hi;
    *(__nv_bfloat162*)&g_xs[N + i] = lo;
}

// ---------------- weight transpose + split (64x64 tiles, coalesced) ----------
__global__ void trans_w_kernel(const float* __restrict__ q,
                               const float* __restrict__ k,
                               const float* __restrict__ v) {
    __shared__ float t[64][65];
    int bz = blockIdx.z;
    int which = bz >> 4, h = bz & 15;
    const float* W = (which == 0 ? q : which == 1 ? k : v) + (size_t)h * DM * DQK;
    int kk0 = blockIdx.x * 64, e0 = blockIdx.y * 64;
    int tx = threadIdx.x, ty = threadIdx.y;
    const size_t WS = (size_t)NCAT * DM;
#pragma unroll
    for (int rr = 0; rr < 8; rr++) {
        int row = ty + 8 * rr;
        t[row][tx]      = W[(size_t)(kk0 + row) * DQK + e0 + tx];
        t[row][tx + 32] = W[(size_t)(kk0 + row) * DQK + e0 + tx + 32];
    }
    __syncthreads();
    size_t nbase = (size_t)which * 2048 + h * 128 + e0;
#pragma unroll
    for (int rr = 0; rr < 8; rr++) {
        int n = ty + 8 * rr;
        float v1 = t[2 * tx][n], v2 = t[2 * tx + 1][n];
        __nv_bfloat16 a0, a1, c0, c1;
        split2(v1, a0, a1);
        split2(v2, c0, c1);
        __nv_bfloat162 hi; hi.x = a0; hi.y = c0;
        __nv_bfloat162 lo; lo.x = a1; lo.y = c1;
        size_t o = (nbase + n) * DM + kk0 + 2 * tx;
        *(__nv_bfloat162*)&g_wt[o] = hi;
        *(__nv_bfloat162*)&g_wt[WS + o] = lo;
    }
}
__global__ void trans_o_kernel(const float* __restrict__ o) {
    __shared__ float t[64][65];
    int h = blockIdx.z;
    const float* O = o + (size_t)h * DV * DM;
    int dm0 = blockIdx.x * 64, v0 = blockIdx.y * 64;
    int tx = threadIdx.x, ty = threadIdx.y;
    const size_t OS = (size_t)DM * DM;
#pragma unroll
    for (int rr = 0; rr < 8; rr++) {
        int row = ty + 8 * rr;   // v index
        t[row][tx]      = O[(size_t)(v0 + row) * DM + dm0 + tx];
        t[row][tx + 32] = O[(size_t)(v0 + row) * DM + dm0 + tx + 32];
    }
    __syncthreads();
#pragma unroll
    for (int rr = 0; rr < 8; rr++) {
        int n = ty + 8 * rr;     // dm-local index
        float v1 = t[2 * tx][n], v2 = t[2 * tx + 1][n];
        __nv_bfloat16 a0, a1, c0, c1;
        split2(v1, a0, a1);
        split2(v2, c0, c1);
        __nv_bfloat162 hi; hi.x = a0; hi.y = c0;
        __nv_bfloat162 lo; lo.x = a1; lo.y = c1;
        size_t oo = (size_t)(dm0 + n) * DM + h * 128 + v0 + 2 * tx;
        *(__nv_bfloat162*)&g_ot[oo] = hi;
        *(__nv_bfloat162*)&g_ot[OS + oo] = lo;
    }
}

// ---------------- bf16x2 mma.sync GEMM (128x128 tile, BK=32, 2 CTAs/SM) ------
// Stage (32KB): A 128 rows x [A0 64B | A1 64B]; B likewise at +16KB.
// 8 warps (2 wm x 4 wn), warp tile 64x32, acc = 64 regs.
// mode 0: fused epilogue RoPE+split -> g_qs2/g_ks2/g_vs2
// mode 1: fp32 epilogue -> Cout * 1/2048
#define GSM_BYTES 65536
#define NKC 64

__global__ void __launch_bounds__(256, 2) gemm2_kernel(float* Cout, int mode) {
    extern __shared__ char gsm[];
    const __nv_bfloat16 *A3, *B3;
    size_t As, Bs;
    if (mode == 0) {
        A3 = g_xs; As = (size_t)SEQ * DM;
        B3 = g_wt; Bs = (size_t)NCAT * DM;
    } else {
        A3 = g_ys; As = (size_t)SEQ * DM;
        B3 = g_ot; Bs = (size_t)DM * DM;
    }

    uint32_t sb = smem_u32(gsm);
    int tid = threadIdx.x;
    int lane = tid & 31, wid = tid >> 5;
    int wm = wid >> 2, wn = wid & 3;          // 2 x 4 warp grid
    int m0 = blockIdx.x * 128, n0 = blockIdx.y * 128;

    float acc[4][4][4];
#pragma unroll
    for (int i = 0; i < 4; i++)
#pragma unroll
        for (int j = 0; j < 4; j++)
#pragma unroll
            for (int r = 0; r < 4; r++) acc[i][j][r] = 0.0f;

    auto load_stage = [&](int st, int kc) {
        int k0 = kc * 32;
        uint32_t base = sb + st * 32768;
        // A: 128 rows x 8 chunks (ch = p*4 + c), 1024 chunks
#pragma unroll
        for (int i = 0; i < 4; i++) {
            int idx = i * 256 + tid;
            int row = idx >> 3, ch = idx & 7;
            int p = ch >> 2, c = ch & 3;
            uint32_t dst = base + row * 128 + ((ch ^ (row & 7)) << 4);
            CP_ASYNC16(dst, A3 + p * As + (size_t)(m0 + row) * DM + k0 + c * 8);
        }
        // B: 128 rows x 8 chunks
#pragma unroll
        for (int i = 0; i < 4; i++) {
            int idx = i * 256 + tid;
            int row = idx >> 3, ch = idx & 7;
            int p = ch >> 2, c = ch & 3;
            uint32_t dst = base + 16384 + row * 128 + ((ch ^ (row & 7)) << 4);
            CP_ASYNC16(dst, B3 + p * Bs + (size_t)(n0 + row) * DM + k0 + c * 8);
        }
    };

    load_stage(0, 0); CP_COMMIT();

    for (int kc = 0; kc < NKC; kc++) {
        int st = kc & 1;
        if (kc + 1 < NKC) { load_stage(st ^ 1, kc + 1); CP_COMMIT(); CP_WAIT(1); }
        else              { CP_WAIT(0); }
        __syncthreads();

        uint32_t stage = sb + st * 32768;
        uint32_t stageB = stage + 16384;
#pragma unroll
        for (int ks = 0; ks < 2; ks++) {
            // B fragments (2 n-frags x 2 planes)
            uint32_t b0[2][4], b1[2][4];
#pragma unroll
            for (int nf2 = 0; nf2 < 2; nf2++) {
                int r = wn * 32 + nf2 * 16 + (lane & 7) + ((lane >> 4) & 1) * 8;
                int ci0 = (0 + ks * 2 + ((lane >> 3) & 1)) ^ (r & 7);
                int ci1 = (4 + ks * 2 + ((lane >> 3) & 1)) ^ (r & 7);
                ldsm4(b0[nf2], stageB + r * 128 + (ci0 << 4));
                ldsm4(b1[nf2], stageB + r * 128 + (ci1 << 4));
            }
            // A plane 0, products A0B0 + A0B1
            uint32_t a0[4][4];
#pragma unroll
            for (int mf = 0; mf < 4; mf++) {
                int r = wm * 64 + mf * 16 + (lane & 15);
                int ci = (0 + ks * 2 + (lane >> 4)) ^ (r & 7);
                ldsm4(a0[mf], stage + r * 128 + (ci << 4));
            }
#pragma unroll
            for (int mf = 0; mf < 4; mf++)
#pragma unroll
                for (int nf2 = 0; nf2 < 2; nf2++) {
                    mma_bf16(acc[mf][2 * nf2 + 0], a0[mf], b0[nf2][0], b0[nf2][1]);
                    mma_bf16(acc[mf][2 * nf2 + 1], a0[mf], b0[nf2][2], b0[nf2][3]);
                    mma_bf16(acc[mf][2 * nf2 + 0], a0[mf], b1[nf2][0], b1[nf2][1]);
                    mma_bf16(acc[mf][2 * nf2 + 1], a0[mf], b1[nf2][2], b1[nf2][3]);
                }
            // A plane 1, product A1B0
            uint32_t a1[4][4];
#pragma unroll
            for (int mf = 0; mf < 4; mf++) {
                int r = wm * 64 + mf * 16 + (lane & 15);
                int ci = (4 + ks * 2 + (lane >> 4)) ^ (r & 7);
                ldsm4(a1[mf], stage + r * 128 + (ci << 4));
            }
#pragma unroll
            for (int mf = 0; mf < 4; mf++)
#pragma unroll
                for (int nf2 = 0; nf2 < 2; nf2++) {
                    mma_bf16(acc[mf][2 * nf2 + 0], a1[mf], b0[nf2][0], b0[nf2][1]);
                    mma_bf16(acc[mf][2 * nf2 + 1], a1[mf], b0[nf2][2], b0[nf2][3]);
                }
        }
        __syncthreads();
    }

    if (mode == 1) {
        const float alpha = 1.0f / 2048.0f;
#pragma unroll
        for (int mf = 0; mf < 4; mf++) {
            int r0 = m0 + wm * 64 + mf * 16 + (lane >> 2);
#pragma unroll
            for (int nf = 0; nf < 4; nf++) {
                int cb = n0 + wn * 32 + nf * 8 + (lane & 3) * 2;
                float2 v01 = make_float2(acc[mf][nf][0] * alpha, acc[mf][nf][1] * alpha);
                float2 v23 = make_float2(acc[mf][nf][2] * alpha, acc[mf][nf][3] * alpha);
                *(float2*)&Cout[(size_t)r0 * DM + cb] = v01;
                *(float2*)&Cout[(size_t)(r0 + 8) * DM + cb] = v23;
            }
        }
        return;
    }

    // ---- fused epilogue (mode 0): stage fp32 tile in smem (XOR-swizzled),
    //      RoPE + split, write q/k/v bf16 planes ----
    float* sm = (float*)gsm;   // 128 x 128 floats = 64KB (reuses stage buffers)
#pragma unroll
    for (int mf = 0; mf < 4; mf++) {
        int r0 = wm * 64 + mf * 16 + (lane >> 2);
#pragma unroll
        for (int nf = 0; nf < 4; nf++) {
            int cb = wn * 32 + nf * 8 + (lane & 3) * 2;
            int i0 = (cb + r0 * 8) & 127;
            int i1 = (cb + (r0 + 8) * 8) & 127;
            sm[r0 * 128 + i0]           = acc[mf][nf][0];
            sm[r0 * 128 + i0 + 1]       = acc[mf][nf][1];
            sm[(r0 + 8) * 128 + i1]     = acc[mf][nf][2];
            sm[(r0 + 8) * 128 + i1 + 1] = acc[mf][nf][3];
        }
    }
    __syncthreads();

    int which = n0 >> 11;            // 0=q 1=k 2=v
    int h = (n0 >> 7) & 15;
    const size_t HSD = (size_t)NH * SEQ * 128;
    const float dq4 = 3.3635856610148585f;   // 128^0.25
    int j0 = 2 * lane;               // 0..62

    for (int i = 0; i < 16; i++) {
        int row = wid * 16 + i;
        int s = m0 + row;
        size_t obase = ((size_t)h * SEQ + s) * 128;
        int ia = (j0 + row * 8) & 127;
        int ib = (j0 + 64 + row * 8) & 127;
        float2 xa = *(float2*)&sm[row * 128 + ia];
        float2 xb = *(float2*)&sm[row * 128 + ib];
        __nv_bfloat16 a0, a1, c0, c1;
        if (which < 2) {
            float2 sn = *(const float2*)&g_sin[s * 64 + j0];
            float2 cs = *(const float2*)&g_cos[s * 64 + j0];
            float r1a = (cs.x * xa.x - sn.x * xb.x) / dq4;
            float r1b = (cs.y * xa.y - sn.y * xb.y) / dq4;
            float r2a = (sn.x * xa.x + cs.x * xb.x) / dq4;
            float r2b = (sn.y * xa.y + cs.y * xb.y) / dq4;
            __nv_bfloat16* dst = which ? g_ks2 : g_qs2;
            split2(r1a, a0, a1); split2(r1b, c0, c1);
            { __nv_bfloat162 hi; hi.x = a0; hi.y = c0;
              __nv_bfloat162 lo; lo.x = a1; lo.y = c1;
              *(__nv_bfloat162*)&dst[obase + j0] = hi;
              *(__nv_bfloat162*)&dst[HSD + obase + j0] = lo; }
            split2(r2a, a0, a1); split2(r2b, c0, c1);
            { __nv_bfloat162 hi; hi.x = a0; hi.y = c0;
              __nv_bfloat162 lo; lo.x = a1; lo.y = c1;
              *(__nv_bfloat162*)&dst[obase + j0 + 64] = hi;
              *(__nv_bfloat162*)&dst[HSD + obase + j0 + 64] = lo; }
        } else {
            split2(xa.x, a0, a1); split2(xa.y, c0, c1);
            { __nv_bfloat162 hi; hi.x = a0; hi.y = c0;
              __nv_bfloat162 lo; lo.x = a1; lo.y = c1;
              *(__nv_bfloat162*)&g_vs2[obase + j0] = hi;
              *(__nv_bfloat162*)&g_vs2[HSD + obase + j0] = lo; }
            split2(xb.x, a0, a1); split2(xb.y, c0, c1);
            { __nv_bfloat162 hi; hi.x = a0; hi.y = c0;
              __nv_bfloat162 lo; lo.x = a1; lo.y = c1;
              *(__nv_bfloat162*)&g_vs2[obase + j0 + 64] = hi;
              *(__nv_bfloat162*)&g_vs2[HSD + obase + j0 + 64] = lo; }
        }
    }
}

// ---------------- flash attention (bf16x2 mma.sync) --------------------------
#define ATTN_SMEM 196608

__global__ void __launch_bounds__(256, 1) attn_kernel() {
    extern __shared__ char asmem[];
    uint32_t sb = smem_u32(asmem);
    int tid = threadIdx.x, lane = tid & 31, wq = tid >> 5;
    int h = blockIdx.x;
    int qt = 15 - (int)blockIdx.y;    // LPT: heavy q-tiles first
    int q0 = qt * 128;
    const size_t HSD = (size_t)NH * SEQ * 128;

    const __nv_bfloat16* Qg = g_qs2 + ((size_t)h * SEQ + q0) * 128;
    const __nv_bfloat16* Kg = g_ks2 + (size_t)h * SEQ * 128;
    const __nv_bfloat16* Vg = g_vs2 + (size_t)h * SEQ * 128;

    const uint32_t Qb = sb;
    const uint32_t St0 = sb + 65536, St1 = sb + 131072;

#define SWZ(base, row, c) ((base) + (row) * 256 + ((((c) ^ (((row) & 7) << 1)) & 15) << 4))

#pragma unroll
    for (int i = 0; i < 16; i++) {
        int idx = i * 256 + tid;
        int p = idx >> 11, rem = idx & 2047, row = rem >> 4, c = rem & 15;
        CP_ASYNC16(SWZ(Qb + p * 32768, row, c),
                   (const char*)(Qg + p * HSD) + row * 256 + c * 16);
    }
    int nkt = 2 * qt + 2;

    auto loadKV = [&](uint32_t stage, int kt) {
        int kb = kt * 64;
#pragma unroll
        for (int i = 0; i < 16; i++) {
            int idx = i * 256 + tid;
            int tile = idx >> 11;
            int p = (idx >> 10) & 1, row = (idx >> 4) & 63, c = idx & 15;
            const __nv_bfloat16* src =
                (tile ? Vg : Kg) + p * HSD + (size_t)(kb + row) * 128;
            CP_ASYNC16(SWZ(stage + tile * 32768 + p * 16384, row, c),
                       (const char*)src + c * 16);
        }
    };
    loadKV(St0, 0); CP_COMMIT();
    loadKV(St1, 1); CP_COMMIT();

    float y[16][4];
#pragma unroll
    for (int i = 0; i < 16; i++)
#pragma unroll
        for (int r = 0; r < 4; r++) y[i][r] = 0.0f;
    float mr0 = -INFINITY, mr1 = -INFINITY, l0 = 0.0f, l1 = 0.0f;
    int qrow0 = q0 + wq * 16 + (lane >> 2);

    for (int kt = 0; kt < nkt; kt++) {
        CP_WAIT(1);
        __syncthreads();
        uint32_t S = (kt & 1) ? St1 : St0;
        int kbase = kt * 64;

        float sacc[8][4];
#pragma unroll
        for (int i = 0; i < 8; i++)
#pragma unroll
            for (int r = 0; r < 4; r++) sacc[i][r] = 0.0f;

#pragma unroll
        for (int kf = 0; kf < 8; kf++) {
            uint32_t aq0[4], aq1[4];
            {
                int row = wq * 16 + (lane & 15);
                int c = kf * 2 + (lane >> 4);
                ldsm4(aq0, SWZ(Qb, row, c));
                ldsm4(aq1, SWZ(Qb + 32768, row, c));
            }
#pragma unroll
            for (int ng = 0; ng < 4; ng++) {
                uint32_t kb0[4], kb1[4];
                int row = ng * 16 + (lane & 7) + ((lane >> 4) & 1) * 8;
                int c = kf * 2 + ((lane >> 3) & 1);
                ldsm4(kb0, SWZ(S, row, c));
                ldsm4(kb1, SWZ(S + 16384, row, c));
                mma_bf16(sacc[2 * ng + 0], aq0, kb0[0], kb0[1]);
                mma_bf16(sacc[2 * ng + 1], aq0, kb0[2], kb0[3]);
                mma_bf16(sacc[2 * ng + 0], aq0, kb1[0], kb1[1]);
                mma_bf16(sacc[2 * ng + 1], aq0, kb1[2], kb1[3]);
                mma_bf16(sacc[2 * ng + 0], aq1, kb0[0], kb0[1]);
                mma_bf16(sacc[2 * ng + 1], aq1, kb0[2], kb0[3]);
            }
        }

        if (kbase + 64 > q0 + wq * 16) {
#pragma unroll
            for (int nf = 0; nf < 8; nf++) {
                int col = kbase + nf * 8 + (lane & 3) * 2;
                if (col > qrow0)         sacc[nf][0] -= 1.0e9f;
                if (col + 1 > qrow0)     sacc[nf][1] -= 1.0e9f;
                if (col > qrow0 + 8)     sacc[nf][2] -= 1.0e9f;
                if (col + 1 > qrow0 + 8) sacc[nf][3] -= 1.0e9f;
            }
        }

        float mx0 = -INFINITY, mx1 = -INFINITY;
#pragma unroll
        for (int nf = 0; nf < 8; nf++) {
            mx0 = fmaxf(mx0, fmaxf(sacc[nf][0], sacc[nf][1]));
            mx1 = fmaxf(mx1, fmaxf(sacc[nf][2], sacc[nf][3]));
        }
        mx0 = fmaxf(mx0, __shfl_xor_sync(0xffffffffu, mx0, 1));
        mx0 = fmaxf(mx0, __shfl_xor_sync(0xffffffffu, mx0, 2));
        mx1 = fmaxf(mx1, __shfl_xor_sync(0xffffffffu, mx1, 1));
        mx1 = fmaxf(mx1, __shfl_xor_sync(0xffffffffu, mx1, 2));
        float mn0 = fmaxf(mr0, mx0), mn1 = fmaxf(mr1, mx1);
        float c0 = __expf(mr0 - mn0), c1 = __expf(mr1 - mn1);
        float ls0 = 0.0f, ls1 = 0.0f;
#pragma unroll
        for (int nf = 0; nf < 8; nf++) {
            sacc[nf][0] = __expf(sacc[nf][0] - mn0);
            sacc[nf][1] = __expf(sacc[nf][1] - mn0);
            sacc[nf][2] = __expf(sacc[nf][2] - mn1);
            sacc[nf][3] = __expf(sacc[nf][3] - mn1);
            ls0 += sacc[nf][0] + sacc[nf][1];
            ls1 += sacc[nf][2] + sacc[nf][3];
        }
        ls0 += __shfl_xor_sync(0xffffffffu, ls0, 1);
        ls0 += __shfl_xor_sync(0xffffffffu, ls0, 2);
        ls1 += __shfl_xor_sync(0xffffffffu, ls1, 1);
        ls1 += __shfl_xor_sync(0xffffffffu, ls1, 2);
        l0 = l0 * c0 + ls0; l1 = l1 * c1 + ls1;
        mr0 = mn0; mr1 = mn1;
#pragma unroll
        for (int i = 0; i < 16; i++) {
            y[i][0] *= c0; y[i][1] *= c0; y[i][2] *= c1; y[i][3] *= c1;
        }

#pragma unroll
        for (int kf2 = 0; kf2 < 4; kf2++) {
            uint32_t p0[4], p1[4];
#pragma unroll
            for (int half = 0; half < 2; half++) {
                float f0 = sacc[2 * kf2 + half][0], f1 = sacc[2 * kf2 + half][1];
                float f2 = sacc[2 * kf2 + half][2], f3 = sacc[2 * kf2 + half][3];
                float g0 = f0 - __bfloat162float(__float2bfloat16(f0));
                float g1 = f1 - __bfloat162float(__float2bfloat16(f1));
                float g2 = f2 - __bfloat162float(__float2bfloat16(f2));
                float g3 = f3 - __bfloat162float(__float2bfloat16(f3));
                p0[2 * half + 0] = pack_bf16x2(f0, f1);
                p0[2 * half + 1] = pack_bf16x2(f2, f3);
                p1[2 * half + 0] = pack_bf16x2(g0, g1);
                p1[2 * half + 1] = pack_bf16x2(g2, g3);
            }
            uint32_t a0[4] = {p0[0], p0[1], p0[2], p0[3]};
            uint32_t a1[4] = {p1[0], p1[1], p1[2], p1[3]};
#pragma unroll
            for (int ng = 0; ng < 8; ng++) {
                uint32_t vb0[4], vb1[4];
                int row = kf2 * 16 + (lane & 15);
                int c = ng * 2 + (lane >> 4);
                ldsm4t(vb0, SWZ(S + 32768, row, c));
                ldsm4t(vb1, SWZ(S + 49152, row, c));
                mma_bf16(y[2 * ng + 0], a0, vb0[0], vb0[1]);
                mma_bf16(y[2 * ng + 1], a0, vb0[2], vb0[3]);
                mma_bf16(y[2 * ng + 0], a0, vb1[0], vb1[1]);
                mma_bf16(y[2 * ng + 1], a0, vb1[2], vb1[3]);
                mma_bf16(y[2 * ng + 0], a1, vb0[0], vb0[1]);
                mma_bf16(y[2 * ng + 1], a1, vb0[2], vb0[3]);
            }
        }

        __syncthreads();
        if (kt + 2 < nkt) loadKV((kt & 1) ? St1 : St0, kt + 2);
        CP_COMMIT();
    }

    float inv0 = 1.0f / l0, inv1 = 1.0f / l1;
    int s0 = q0 + wq * 16 + (lane >> 2);
    const size_t N = (size_t)SEQ * DM;
#pragma unroll
    for (int nf = 0; nf < 16; nf++) {
        int col = h * 128 + nf * 8 + (lane & 3) * 2;
        {
            float f0 = y[nf][0] * inv0, f1 = y[nf][1] * inv0;
            __nv_bfloat16 a0 = __float2bfloat16(f0), a1 = __float2bfloat16(f1);
            __nv_bfloat162 hi; hi.x = a0; hi.y = a1;
            __nv_bfloat162 lo;
            lo.x = __float2bfloat16(f0 - __bfloat162float(a0));
            lo.y = __float2bfloat16(f1 - __bfloat162float(a1));
            *(__nv_bfloat162*)&g_ys[(size_t)s0 * DM + col] = hi;
            *(__nv_bfloat162*)&g_ys[N + (size_t)s0 * DM + col] = lo;
        }
        {
            float f0 = y[nf][2] * inv1, f1 = y[nf][3] * inv1;
            __nv_bfloat16 a0 = __float2bfloat16(f0), a1 = __float2bfloat16(f1);
            __nv_bfloat162 hi; hi.x = a0; hi.y = a1;
            __nv_bfloat162 lo;
            lo.x = __float2bfloat16(f0 - __bfloat162float(a0));
            lo.y = __float2bfloat16(f1 - __bfloat162float(a1));
            *(__nv_bfloat162*)&g_ys[(size_t)(s0 + 8) * DM + col] = hi;
            *(__nv_bfloat162*)&g_ys[N + (size_t)(s0 + 8) * DM + col] = lo;
        }
    }
#undef SWZ
}

// ---------------- launch ----------------------------------------------------
extern "C" void kernel_launch(void* const* d_in, const int* in_sizes, int n_in,
                              void* d_out, int out_size) {
    const float* x     = (const float*)d_in[0];
    const float* q     = (const float*)d_in[1];
    const float* k     = (const float*)d_in[2];
    const float* v     = (const float*)d_in[3];
    const float* o     = (const float*)d_in[4];
    const float* theta = (const float*)d_in[5];
    float* z = (float*)d_out;

    cudaFuncSetAttribute(attn_kernel,
                         cudaFuncAttributeMaxDynamicSharedMemorySize, ATTN_SMEM);
    cudaFuncSetAttribute(gemm2_kernel,
                         cudaFuncAttributeMaxDynamicSharedMemorySize, GSM_BYTES);

    // gemm0 is the 4th launch -> lands in the ncu-profiled slot
    rope_table_kernel<<<(SEQ * 64 + 255) / 256, 256>>>(theta);
    split_x_kernel<<<(SEQ * DM / 2) / 256, 256>>>(x);
    trans_w_kernel<<<dim3(32, 2, 48), dim3(32, 8)>>>(q, k, v);
    gemm2_kernel<<<dim3(16, 48), 256, GSM_BYTES>>>(nullptr, 0);
    trans_o_kernel<<<dim3(32, 2, 16), dim3(32, 8)>>>(o);
    attn_kernel<<<dim3(NH, 16), 256, ATTN_SMEM>>>();
    gemm2_kernel<<<dim3(16, 16), 256, GSM_BYTES>>>(z, 1);
}

// round 15
// speedup vs baseline: 1.0630x; 1.0630x over previous
#include <cuda_runtime.h>
#include <cuda_bf16.h>
#include <math.h>
#include <cstdint>

#define SEQ 2048
#define DM  2048
#define NH  16
#define DQK 128
#define DV  128
#define NCAT 6144   // q|k|v concatenated head-columns

// ---------------- helpers ----------------------------------------------------
__device__ __forceinline__ uint32_t smem_u32(const void* p) {
    uint32_t a;
    asm("{ .reg .u64 t; cvta.to.shared.u64 t, %1; cvt.u32.u64 %0, t; }"
        : "=r"(a) : "l"(p));
    return a;
}

#define CP_ASYNC16(dst, src) \
    asm volatile("cp.async.cg.shared.global [%0], [%1], 16;" :: "r"(dst), "l"(src))
#define CP_COMMIT() asm volatile("cp.async.commit_group;" ::: "memory")
#define CP_WAIT(n)  asm volatile("cp.async.wait_group %0;" :: "n"(n) : "memory")

__device__ __forceinline__ void ldsm4(uint32_t* r, uint32_t addr) {
    asm volatile("ldmatrix.sync.aligned.m8n8.x4.shared.b16 {%0,%1,%2,%3}, [%4];"
                 : "=r"(r[0]), "=r"(r[1]), "=r"(r[2]), "=r"(r[3]) : "r"(addr));
}
__device__ __forceinline__ void ldsm4t(uint32_t* r, uint32_t addr) {
    asm volatile("ldmatrix.sync.aligned.m8n8.x4.trans.shared.b16 {%0,%1,%2,%3}, [%4];"
                 : "=r"(r[0]), "=r"(r[1]), "=r"(r[2]), "=r"(r[3]) : "r"(addr));
}

__device__ __forceinline__ void mma_bf16(float* d, const uint32_t* a,
                                         uint32_t b0, uint32_t b1) {
    asm volatile(
        "mma.sync.aligned.m16n8k16.row.col.f32.bf16.bf16.f32 "
        "{%0,%1,%2,%3}, {%4,%5,%6,%7}, {%8,%9}, {%0,%1,%2,%3};"
        : "+f"(d[0]), "+f"(d[1]), "+f"(d[2]), "+f"(d[3])
        : "r"(a[0]), "r"(a[1]), "r"(a[2]), "r"(a[3]), "r"(b0), "r"(b1));
}

__device__ __forceinline__ uint32_t pack_bf16x2(float lo, float hi) {
    uint32_t d;
    asm("cvt.rn.bf16x2.f32 %0, %1, %2;" : "=r"(d) : "f"(hi), "f"(lo));
    return d;
}

// ---------------- scratch (device globals) ----------------------------------
__device__ __align__(256) __nv_bfloat16 g_xs[2ull * SEQ * DM];
__device__ __align__(256) __nv_bfloat16 g_wt[2ull * NCAT * DM];
__device__ __align__(256) __nv_bfloat16 g_ot[2ull * DM * DM];
__device__ __align__(256) __nv_bfloat16 g_ys[2ull * SEQ * DM];
__device__ __align__(256) __nv_bfloat16 g_qs2[2ull * NH * SEQ * DQK];
__device__ __align__(256) __nv_bfloat16 g_ks2[2ull * NH * SEQ * DQK];
__device__ __align__(256) __nv_bfloat16 g_vs2[2ull * NH * SEQ * DV];
__device__ __align__(256) float g_pqkv[(size_t)SEQ * NCAT];
__device__ float g_sin[SEQ * 64];
__device__ float g_cos[SEQ * 64];

// ---------------- bf16x2 split ----------------------------------------------
__device__ __forceinline__ void split2(float x, __nv_bfloat16& b0, __nv_bfloat16& b1) {
    b0 = __float2bfloat16(x);
    float r = x - __bfloat162float(b0);
    b1 = __float2bfloat16(r);
}

// ---------------- merged prep: rope table | split x | trans w | trans o ------
// blocks: [0,512) rope_table; [512,8704) split_x; [8704,11776) trans_w;
//         [11776,12800) trans_o.  256 threads each.
__global__ void prep_all_kernel(const float* __restrict__ x,
                                const float* __restrict__ q,
                                const float* __restrict__ k,
                                const float* __restrict__ v,
                                const float* __restrict__ o,
                                const float* __restrict__ theta_p) {
    __shared__ float t[64][65];
    int b = blockIdx.x;
    int tid = threadIdx.x;

    if (b < 512) {
        int idx = b * 256 + tid;
        int j = idx & 63;
        int s = idx >> 6;
        float theta = *theta_p;
        float rate = theta * (-(float)j / 64.0f);
        float rot  = (float)s * rate;
        double rd = (double)rot;
        g_sin[idx] = (float)sin(rd);
        g_cos[idx] = (float)cos(rd);
        return;
    }
    if (b < 8704) {
        int i = ((b - 512) * 256 + tid) * 2;
        const size_t N = (size_t)SEQ * DM;
        float2 xv = *(const float2*)&x[i];
        __nv_bfloat16 a0, a1, c0, c1;
        split2(xv.x, a0, a1);
        split2(xv.y, c0, c1);
        __nv_bfloat162 hi; hi.x = a0; hi.y = c0;
        __nv_bfloat162 lo; lo.x = a1; lo.y = c1;
        *(__nv_bfloat162*)&g_xs[i] = hi;
        *(__nv_bfloat162*)&g_xs[N + i] = lo;
        return;
    }
    int tx = tid & 31, ty = tid >> 5;
    if (b < 11776) {
        int bb = b - 8704;
        int bx = bb & 31, by = (bb >> 5) & 1, bz = bb >> 6;
        int which = bz >> 4, h = bz & 15;
        const float* W = (which == 0 ? q : which == 1 ? k : v) + (size_t)h * DM * DQK;
        int kk0 = bx * 64, e0 = by * 64;
        const size_t WS = (size_t)NCAT * DM;
#pragma unroll
        for (int rr = 0; rr < 8; rr++) {
            int row = ty + 8 * rr;
            t[row][tx]      = W[(size_t)(kk0 + row) * DQK + e0 + tx];
            t[row][tx + 32] = W[(size_t)(kk0 + row) * DQK + e0 + tx + 32];
        }
        __syncthreads();
        size_t nbase = (size_t)which * 2048 + h * 128 + e0;
#pragma unroll
        for (int rr = 0; rr < 8; rr++) {
            int n = ty + 8 * rr;
            float v1 = t[2 * tx][n], v2 = t[2 * tx + 1][n];
            __nv_bfloat16 a0, a1, c0, c1;
            split2(v1, a0, a1);
            split2(v2, c0, c1);
            __nv_bfloat162 hi; hi.x = a0; hi.y = c0;
            __nv_bfloat162 lo; lo.x = a1; lo.y = c1;
            size_t oo = (nbase + n) * DM + kk0 + 2 * tx;
            *(__nv_bfloat162*)&g_wt[oo] = hi;
            *(__nv_bfloat162*)&g_wt[WS + oo] = lo;
        }
        return;
    }
    {
        int bb = b - 11776;
        int bx = bb & 31, by = (bb >> 5) & 1, h = bb >> 6;
        const float* O = o + (size_t)h * DV * DM;
        int dm0 = bx * 64, v0 = by * 64;
        const size_t OS = (size_t)DM * DM;
#pragma unroll
        for (int rr = 0; rr < 8; rr++) {
            int row = ty + 8 * rr;
            t[row][tx]      = O[(size_t)(v0 + row) * DM + dm0 + tx];
            t[row][tx + 32] = O[(size_t)(v0 + row) * DM + dm0 + tx + 32];
        }
        __syncthreads();
#pragma unroll
        for (int rr = 0; rr < 8; rr++) {
            int n = ty + 8 * rr;
            float v1 = t[2 * tx][n], v2 = t[2 * tx + 1][n];
            __nv_bfloat16 a0, a1, c0, c1;
            split2(v1, a0, a1);
            split2(v2, c0, c1);
            __nv_bfloat162 hi; hi.x = a0; hi.y = c0;
            __nv_bfloat162 lo; lo.x = a1; lo.y = c1;
            size_t oo = (size_t)(dm0 + n) * DM + h * 128 + v0 + 2 * tx;
            *(__nv_bfloat162*)&g_ot[oo] = hi;
            *(__nv_bfloat162*)&g_ot[OS + oo] = lo;
        }
    }
}

// ---------------- gemm0: R9 config (256x128 tile, BK=64, 2-stage) ------------
#define GSM0_BYTES (2 * 98304)

__global__ void __launch_bounds__(256, 1) gemm0_kernel() {
    extern __shared__ char gsm[];
    const __nv_bfloat16* A3 = g_xs;
    const __nv_bfloat16* B3 = g_wt;
    const size_t As = (size_t)SEQ * DM;
    const size_t Bs = (size_t)NCAT * DM;
    float* C = g_pqkv;
    const int ldc = NCAT;

    uint32_t sb = smem_u32(gsm);
    int tid = threadIdx.x;
    int lane = tid & 31, wid = tid >> 5;
    int wm = wid >> 1, wn = wid & 1;
    int m0 = blockIdx.x * 256, n0 = blockIdx.y * 128;

    float acc[4][8][4];
#pragma unroll
    for (int i = 0; i < 4; i++)
#pragma unroll
        for (int j = 0; j < 8; j++)
#pragma unroll
            for (int r = 0; r < 4; r++) acc[i][j][r] = 0.0f;

    auto load_stage = [&](int s, int kc) {
        int k0 = kc * 64;
#pragma unroll
        for (int p = 0; p < 2; p++) {
            const __nv_bfloat16* gp = A3 + p * As + (size_t)m0 * DM + k0;
            uint32_t base = sb + s * 98304 + p * 32768;
#pragma unroll
            for (int i = 0; i < 8; i++) {
                int idx = i * 256 + tid;
                int row = idx >> 3, c = idx & 7;
                uint32_t dst = base + row * 128 + ((c ^ (row & 7)) << 4);
                CP_ASYNC16(dst, gp + (size_t)row * DM + c * 8);
            }
        }
#pragma unroll
        for (int p = 0; p < 2; p++) {
            const __nv_bfloat16* gp = B3 + p * Bs + (size_t)n0 * DM + k0;
            uint32_t base = sb + s * 98304 + 65536 + p * 16384;
#pragma unroll
            for (int i = 0; i < 4; i++) {
                int idx = i * 256 + tid;
                int row = idx >> 3, c = idx & 7;
                uint32_t dst = base + row * 128 + ((c ^ (row & 7)) << 4);
                CP_ASYNC16(dst, gp + (size_t)row * DM + c * 8);
            }
        }
    };

    load_stage(0, 0); CP_COMMIT();

    for (int kc = 0; kc < 32; kc++) {
        int s = kc & 1;
        if (kc + 1 < 32) { load_stage(s ^ 1, kc + 1); CP_COMMIT(); CP_WAIT(1); }
        else            { CP_WAIT(0); }
        __syncthreads();

        uint32_t stage = sb + s * 98304;
#pragma unroll
        for (int ks = 0; ks < 4; ks++) {
            uint32_t a[2][4][4];
#pragma unroll
            for (int p = 0; p < 2; p++)
#pragma unroll
                for (int mf = 0; mf < 4; mf++) {
                    int row = wm * 64 + mf * 16 + (lane & 15);
                    int c = ks * 2 + ((lane >> 4) & 1);
                    uint32_t addr = stage + p * 32768 + row * 128 +
                                    ((c ^ (row & 7)) << 4);
                    ldsm4(a[p][mf], addr);
                }
            uint32_t b[2][4][4];
#pragma unroll
            for (int p = 0; p < 2; p++)
#pragma unroll
                for (int nf2 = 0; nf2 < 4; nf2++) {
                    int row = wn * 64 + nf2 * 16 + (lane & 7) + ((lane >> 4) & 1) * 8;
                    int c = ks * 2 + ((lane >> 3) & 1);
                    uint32_t addr = stage + 65536 + p * 16384 + row * 128 +
                                    ((c ^ (row & 7)) << 4);
                    ldsm4(b[p][nf2], addr);
                }
#pragma unroll
            for (int mf = 0; mf < 4; mf++)
#pragma unroll
                for (int nf2 = 0; nf2 < 4; nf2++) {
                    mma_bf16(acc[mf][2 * nf2 + 0], a[0][mf], b[0][nf2][0], b[0][nf2][1]);
                    mma_bf16(acc[mf][2 * nf2 + 1], a[0][mf], b[0][nf2][2], b[0][nf2][3]);
                    mma_bf16(acc[mf][2 * nf2 + 0], a[0][mf], b[1][nf2][0], b[1][nf2][1]);
                    mma_bf16(acc[mf][2 * nf2 + 1], a[0][mf], b[1][nf2][2], b[1][nf2][3]);
                    mma_bf16(acc[mf][2 * nf2 + 0], a[1][mf], b[0][nf2][0], b[0][nf2][1]);
                    mma_bf16(acc[mf][2 * nf2 + 1], a[1][mf], b[0][nf2][2], b[0][nf2][3]);
                }
        }
        __syncthreads();
    }

#pragma unroll
    for (int mf = 0; mf < 4; mf++) {
        int r0 = m0 + wm * 64 + mf * 16 + (lane >> 2);
#pragma unroll
        for (int nf = 0; nf < 8; nf++) {
            int cb = n0 + wn * 64 + nf * 8 + (lane & 3) * 2;
            float2 v01 = make_float2(acc[mf][nf][0], acc[mf][nf][1]);
            float2 v23 = make_float2(acc[mf][nf][2], acc[mf][nf][3]);
            *(float2*)&C[(size_t)r0 * ldc + cb] = v01;
            *(float2*)&C[(size_t)(r0 + 8) * ldc + cb] = v23;
        }
    }
}

// ---------------- gemm1: R14 config (128x128 tile, BK=32, 2 CTAs/SM) ---------
#define GSM1_BYTES 65536
#define NKC 64

__global__ void __launch_bounds__(256, 2) gemm1_kernel(float* Cout) {
    extern __shared__ char gsm[];
    const __nv_bfloat16* A3 = g_ys;
    const __nv_bfloat16* B3 = g_ot;
    const size_t As = (size_t)SEQ * DM;
    const size_t Bs = (size_t)DM * DM;

    uint32_t sb = smem_u32(gsm);
    int tid = threadIdx.x;
    int lane = tid & 31, wid = tid >> 5;
    int wm = wid >> 2, wn = wid & 3;
    int m0 = blockIdx.x * 128, n0 = blockIdx.y * 128;

    float acc[4][4][4];
#pragma unroll
    for (int i = 0; i < 4; i++)
#pragma unroll
        for (int j = 0; j < 4; j++)
#pragma unroll
            for (int r = 0; r < 4; r++) acc[i][j][r] = 0.0f;

    auto load_stage = [&](int st, int kc) {
        int k0 = kc * 32;
        uint32_t base = sb + st * 32768;
#pragma unroll
        for (int i = 0; i < 4; i++) {
            int idx = i * 256 + tid;
            int row = idx >> 3, ch = idx & 7;
            int p = ch >> 2, c = ch & 3;
            uint32_t dst = base + row * 128 + ((ch ^ (row & 7)) << 4);
            CP_ASYNC16(dst, A3 + p * As + (size_t)(m0 + row) * DM + k0 + c * 8);
        }
#pragma unroll
        for (int i = 0; i < 4; i++) {
            int idx = i * 256 + tid;
            int row = idx >> 3, ch = idx & 7;
            int p = ch >> 2, c = ch & 3;
            uint32_t dst = base + 16384 + row * 128 + ((ch ^ (row & 7)) << 4);
            CP_ASYNC16(dst, B3 + p * Bs + (size_t)(n0 + row) * DM + k0 + c * 8);
        }
    };

    load_stage(0, 0); CP_COMMIT();

    for (int kc = 0; kc < NKC; kc++) {
        int st = kc & 1;
        if (kc + 1 < NKC) { load_stage(st ^ 1, kc + 1); CP_COMMIT(); CP_WAIT(1); }
        else              { CP_WAIT(0); }
        __syncthreads();

        uint32_t stage = sb + st * 32768;
        uint32_t stageB = stage + 16384;
#pragma unroll
        for (int ks = 0; ks < 2; ks++) {
            uint32_t b0[2][4], b1[2][4];
#pragma unroll
            for (int nf2 = 0; nf2 < 2; nf2++) {
                int r = wn * 32 + nf2 * 16 + (lane & 7) + ((lane >> 4) & 1) * 8;
                int ci0 = (0 + ks * 2 + ((lane >> 3) & 1)) ^ (r & 7);
                int ci1 = (4 + ks * 2 + ((lane >> 3) & 1)) ^ (r & 7);
                ldsm4(b0[nf2], stageB + r * 128 + (ci0 << 4));
                ldsm4(b1[nf2], stageB + r * 128 + (ci1 << 4));
            }
            uint32_t a0[4][4];
#pragma unroll
            for (int mf = 0; mf < 4; mf++) {
                int r = wm * 64 + mf * 16 + (lane & 15);
                int ci = (0 + ks * 2 + (lane >> 4)) ^ (r & 7);
                ldsm4(a0[mf], stage + r * 128 + (ci << 4));
            }
#pragma unroll
            for (int mf = 0; mf < 4; mf++)
#pragma unroll
                for (int nf2 = 0; nf2 < 2; nf2++) {
                    mma_bf16(acc[mf][2 * nf2 + 0], a0[mf], b0[nf2][0], b0[nf2][1]);
                    mma_bf16(acc[mf][2 * nf2 + 1], a0[mf], b0[nf2][2], b0[nf2][3]);
                    mma_bf16(acc[mf][2 * nf2 + 0], a0[mf], b1[nf2][0], b1[nf2][1]);
                    mma_bf16(acc[mf][2 * nf2 + 1], a0[mf], b1[nf2][2], b1[nf2][3]);
                }
            uint32_t a1[4][4];
#pragma unroll
            for (int mf = 0; mf < 4; mf++) {
                int r = wm * 64 + mf * 16 + (lane & 15);
                int ci = (4 + ks * 2 + (lane >> 4)) ^ (r & 7);
                ldsm4(a1[mf], stage + r * 128 + (ci << 4));
            }
#pragma unroll
            for (int mf = 0; mf < 4; mf++)
#pragma unroll
                for (int nf2 = 0; nf2 < 2; nf2++) {
                    mma_bf16(acc[mf][2 * nf2 + 0], a1[mf], b0[nf2][0], b0[nf2][1]);
                    mma_bf16(acc[mf][2 * nf2 + 1], a1[mf], b0[nf2][2], b0[nf2][3]);
                }
        }
        __syncthreads();
    }

    const float alpha = 1.0f / 2048.0f;
#pragma unroll
    for (int mf = 0; mf < 4; mf++) {
        int r0 = m0 + wm * 64 + mf * 16 + (lane >> 2);
#pragma unroll
        for (int nf = 0; nf < 4; nf++) {
            int cb = n0 + wn * 32 + nf * 8 + (lane & 3) * 2;
            float2 v01 = make_float2(acc[mf][nf][0] * alpha, acc[mf][nf][1] * alpha);
            float2 v23 = make_float2(acc[mf][nf][2] * alpha, acc[mf][nf][3] * alpha);
            *(float2*)&Cout[(size_t)r0 * DM + cb] = v01;
            *(float2*)&Cout[(size_t)(r0 + 8) * DM + cb] = v23;
        }
    }
}

// ---------------- prep attn: RoPE + bf16x2 split of q,k,v --------------------
__global__ void prep_attn_kernel() {
    int g = blockIdx.x * blockDim.x + threadIdx.x;
    int jp = g & 31;
    int s = (g >> 5) & (SEQ - 1);
    int h = (g >> 16) & (NH - 1);
    int t = g >> 20;                                  // 0=q, 1=k, 2=v
    const float* row = g_pqkv + (size_t)s * NCAT + t * 2048 + h * 128;
    size_t obase = ((size_t)h * SEQ + s) * 128;
    const size_t HSD = (size_t)NH * SEQ * 128;
    int j0 = 2 * jp;
    __nv_bfloat16 a0, a1, c0, c1;
    if (t < 2) {
        float2 x1 = *(const float2*)&row[j0];
        float2 x2 = *(const float2*)&row[j0 + 64];
        float2 sn = *(const float2*)&g_sin[s * 64 + j0];
        float2 cs = *(const float2*)&g_cos[s * 64 + j0];
        const float dq4 = 3.3635856610148585f;
        float r1a = (cs.x * x1.x - sn.x * x2.x) / dq4;
        float r1b = (cs.y * x1.y - sn.y * x2.y) / dq4;
        float r2a = (sn.x * x1.x + cs.x * x2.x) / dq4;
        float r2b = (sn.y * x1.y + cs.y * x2.y) / dq4;
        __nv_bfloat16* dst = (t == 0 ? g_qs2 : g_ks2);
        split2(r1a, a0, a1); split2(r1b, c0, c1);
        { __nv_bfloat162 hi; hi.x = a0; hi.y = c0;
          __nv_bfloat162 lo; lo.x = a1; lo.y = c1;
          *(__nv_bfloat162*)&dst[obase + j0] = hi;
          *(__nv_bfloat162*)&dst[HSD + obase + j0] = lo; }
        split2(r2a, a0, a1); split2(r2b, c0, c1);
        { __nv_bfloat162 hi; hi.x = a0; hi.y = c0;
          __nv_bfloat162 lo; lo.x = a1; lo.y = c1;
          *(__nv_bfloat162*)&dst[obase + j0 + 64] = hi;
          *(__nv_bfloat162*)&dst[HSD + obase + j0 + 64] = lo; }
    } else {
        float2 v1 = *(const float2*)&row[j0];
        float2 v2 = *(const float2*)&row[j0 + 64];
        split2(v1.x, a0, a1); split2(v1.y, c0, c1);
        { __nv_bfloat162 hi; hi.x = a0; hi.y = c0;
          __nv_bfloat162 lo; lo.x = a1; lo.y = c1;
          *(__nv_bfloat162*)&g_vs2[obase + j0] = hi;
          *(__nv_bfloat162*)&g_vs2[HSD + obase + j0] = lo; }
        split2(v2.x, a0, a1); split2(v2.y, c0, c1);
        { __nv_bfloat162 hi; hi.x = a0; hi.y = c0;
          __nv_bfloat162 lo; lo.x = a1; lo.y = c1;
          *(__nv_bfloat162*)&g_vs2[obase + j0 + 64] = hi;
          *(__nv_bfloat162*)&g_vs2[HSD + obase + j0 + 64] = lo; }
    }
}

// ---------------- flash attention (bf16x2 mma.sync) --------------------------
#define ATTN_SMEM 196608

__global__ void __launch_bounds__(256, 1) attn_kernel() {
    extern __shared__ char asmem[];
    uint32_t sb = smem_u32(asmem);
    int tid = threadIdx.x, lane = tid & 31, wq = tid >> 5;
    int h = blockIdx.x;
    int qt = 15 - (int)blockIdx.y;    // LPT: heavy q-tiles first
    int q0 = qt * 128;
    const size_t HSD = (size_t)NH * SEQ * 128;

    const __nv_bfloat16* Qg = g_qs2 + ((size_t)h * SEQ + q0) * 128;
    const __nv_bfloat16* Kg = g_ks2 + (size_t)h * SEQ * 128;
    const __nv_bfloat16* Vg = g_vs2 + (size_t)h * SEQ * 128;

    const uint32_t Qb = sb;
    const uint32_t St0 = sb + 65536, St1 = sb + 131072;

#define SWZ(base, row, c) ((base) + (row) * 256 + ((((c) ^ (((row) & 7) << 1)) & 15) << 4))

#pragma unroll
    for (int i = 0; i < 16; i++) {
        int idx = i * 256 + tid;
        int p = idx >> 11, rem = idx & 2047, row = rem >> 4, c = rem & 15;
        CP_ASYNC16(SWZ(Qb + p * 32768, row, c),
                   (const char*)(Qg + p * HSD) + row * 256 + c * 16);
    }
    int nkt = 2 * qt + 2;

    auto loadKV = [&](uint32_t stage, int kt) {
        int kb = kt * 64;
#pragma unroll
        for (int i = 0; i < 16; i++) {
            int idx = i * 256 + tid;
            int tile = idx >> 11;
            int p = (idx >> 10) & 1, row = (idx >> 4) & 63, c = idx & 15;
            const __nv_bfloat16* src =
                (tile ? Vg : Kg) + p * HSD + (size_t)(kb + row) * 128;
            CP_ASYNC16(SWZ(stage + tile * 32768 + p * 16384, row, c),
                       (const char*)src + c * 16);
        }
    };
    loadKV(St0, 0); CP_COMMIT();
    loadKV(St1, 1); CP_COMMIT();

    float y[16][4];
#pragma unroll
    for (int i = 0; i < 16; i++)
#pragma unroll
        for (int r = 0; r < 4; r++) y[i][r] = 0.0f;
    float mr0 = -INFINITY, mr1 = -INFINITY, l0 = 0.0f, l1 = 0.0f;
    int qrow0 = q0 + wq * 16 + (lane >> 2);

    for (int kt = 0; kt < nkt; kt++) {
        CP_WAIT(1);
        __syncthreads();
        uint32_t S = (kt & 1) ? St1 : St0;
        int kbase = kt * 64;

        float sacc[8][4];
#pragma unroll
        for (int i = 0; i < 8; i++)
#pragma unroll
            for (int r = 0; r < 4; r++) sacc[i][r] = 0.0f;

#pragma unroll
        for (int kf = 0; kf < 8; kf++) {
            uint32_t aq0[4], aq1[4];
            {
                int row = wq * 16 + (lane & 15);
                int c = kf * 2 + (lane >> 4);
                ldsm4(aq0, SWZ(Qb, row, c));
                ldsm4(aq1, SWZ(Qb + 32768, row, c));
            }
#pragma unroll
            for (int ng = 0; ng < 4; ng++) {
                uint32_t kb0[4], kb1[4];
                int row = ng * 16 + (lane & 7) + ((lane >> 4) & 1) * 8;
                int c = kf * 2 + ((lane >> 3) & 1);
                ldsm4(kb0, SWZ(S, row, c));
                ldsm4(kb1, SWZ(S + 16384, row, c));
                mma_bf16(sacc[2 * ng + 0], aq0, kb0[0], kb0[1]);
                mma_bf16(sacc[2 * ng + 1], aq0, kb0[2], kb0[3]);
                mma_bf16(sacc[2 * ng + 0], aq0, kb1[0], kb1[1]);
                mma_bf16(sacc[2 * ng + 1], aq0, kb1[2], kb1[3]);
                mma_bf16(sacc[2 * ng + 0], aq1, kb0[0], kb0[1]);
                mma_bf16(sacc[2 * ng + 1], aq1, kb0[2], kb0[3]);
            }
        }

        if (kbase + 64 > q0 + wq * 16) {
#pragma unroll
            for (int nf = 0; nf < 8; nf++) {
                int col = kbase + nf * 8 + (lane & 3) * 2;
                if (col > qrow0)         sacc[nf][0] -= 1.0e9f;
                if (col + 1 > qrow0)     sacc[nf][1] -= 1.0e9f;
                if (col > qrow0 + 8)     sacc[nf][2] -= 1.0e9f;
                if (col + 1 > qrow0 + 8) sacc[nf][3] -= 1.0e9f;
            }
        }

        float mx0 = -INFINITY, mx1 = -INFINITY;
#pragma unroll
        for (int nf = 0; nf < 8; nf++) {
            mx0 = fmaxf(mx0, fmaxf(sacc[nf][0], sacc[nf][1]));
            mx1 = fmaxf(mx1, fmaxf(sacc[nf][2], sacc[nf][3]));
        }
        mx0 = fmaxf(mx0, __shfl_xor_sync(0xffffffffu, mx0, 1));
        mx0 = fmaxf(mx0, __shfl_xor_sync(0xffffffffu, mx0, 2));
        mx1 = fmaxf(mx1, __shfl_xor_sync(0xffffffffu, mx1, 1));
        mx1 = fmaxf(mx1, __shfl_xor_sync(0xffffffffu, mx1, 2));
        float mn0 = fmaxf(mr0, mx0), mn1 = fmaxf(mr1, mx1);
        float c0 = __expf(mr0 - mn0), c1 = __expf(mr1 - mn1);
        float ls0 = 0.0f, ls1 = 0.0f;
#pragma unroll
        for (int nf = 0; nf < 8; nf++) {
            sacc[nf][0] = __expf(sacc[nf][0] - mn0);
            sacc[nf][1] = __expf(sacc[nf][1] - mn0);
            sacc[nf][2] = __expf(sacc[nf][2] - mn1);
            sacc[nf][3] = __expf(sacc[nf][3] - mn1);
            ls0 += sacc[nf][0] + sacc[nf][1];
            ls1 += sacc[nf][2] + sacc[nf][3];
        }
        ls0 += __shfl_xor_sync(0xffffffffu, ls0, 1);
        ls0 += __shfl_xor_sync(0xffffffffu, ls0, 2);
        ls1 += __shfl_xor_sync(0xffffffffu, ls1, 1);
        ls1 += __shfl_xor_sync(0xffffffffu, ls1, 2);
        l0 = l0 * c0 + ls0; l1 = l1 * c1 + ls1;
        mr0 = mn0; mr1 = mn1;
#pragma unroll
        for (int i = 0; i < 16; i++) {
            y[i][0] *= c0; y[i][1] *= c0; y[i][2] *= c1; y[i][3] *= c1;
        }

#pragma unroll
        for (int kf2 = 0; kf2 < 4; kf2++) {
            uint32_t p0[4], p1[4];
#pragma unroll
            for (int half = 0; half < 2; half++) {
                float f0 = sacc[2 * kf2 + half][0], f1 = sacc[2 * kf2 + half][1];
                float f2 = sacc[2 * kf2 + half][2], f3 = sacc[2 * kf2 + half][3];
                float g0 = f0 - __bfloat162float(__float2bfloat16(f0));
                float g1 = f1 - __bfloat162float(__float2bfloat16(f1));
                float g2 = f2 - __bfloat162float(__float2bfloat16(f2));
                float g3 = f3 - __bfloat162float(__float2bfloat16(f3));
                p0[2 * half + 0] = pack_bf16x2(f0, f1);
                p0[2 * half + 1] = pack_bf16x2(f2, f3);
                p1[2 * half + 0] = pack_bf16x2(g0, g1);
                p1[2 * half + 1] = pack_bf16x2(g2, g3);
            }
            uint32_t a0[4] = {p0[0], p0[1], p0[2], p0[3]};
            uint32_t a1[4] = {p1[0], p1[1], p1[2], p1[3]};
#pragma unroll
            for (int ng = 0; ng < 8; ng++) {
                uint32_t vb0[4], vb1[4];
                int row = kf2 * 16 + (lane & 15);
                int c = ng * 2 + (lane >> 4);
                ldsm4t(vb0, SWZ(S + 32768, row, c));
                ldsm4t(vb1, SWZ(S + 49152, row, c));
                mma_bf16(y[2 * ng + 0], a0, vb0[0], vb0[1]);
                mma_bf16(y[2 * ng + 1], a0, vb0[2], vb0[3]);
                mma_bf16(y[2 * ng + 0], a0, vb1[0], vb1[1]);
                mma_bf16(y[2 * ng + 1], a0, vb1[2], vb1[3]);
                mma_bf16(y[2 * ng + 0], a1, vb0[0], vb0[1]);
                mma_bf16(y[2 * ng + 1], a1, vb0[2], vb0[3]);
            }
        }

        __syncthreads();
        if (kt + 2 < nkt) loadKV((kt & 1) ? St1 : St0, kt + 2);
        CP_COMMIT();
    }

    float inv0 = 1.0f / l0, inv1 = 1.0f / l1;
    int s0 = q0 + wq * 16 + (lane >> 2);
    const size_t N = (size_t)SEQ * DM;
#pragma unroll
    for (int nf = 0; nf < 16; nf++) {
        int col = h * 128 + nf * 8 + (lane & 3) * 2;
        {
            float f0 = y[nf][0] * inv0, f1 = y[nf][1] * inv0;
            __nv_bfloat16 a0 = __float2bfloat16(f0), a1 = __float2bfloat16(f1);
            __nv_bfloat162 hi; hi.x = a0; hi.y = a1;
            __nv_bfloat162 lo;
            lo.x = __float2bfloat16(f0 - __bfloat162float(a0));
            lo.y = __float2bfloat16(f1 - __bfloat162float(a1));
            *(__nv_bfloat162*)&g_ys[(size_t)s0 * DM + col] = hi;
            *(__nv_bfloat162*)&g_ys[N + (size_t)s0 * DM + col] = lo;
        }
        {
            float f0 = y[nf][2] * inv1, f1 = y[nf][3] * inv1;
            __nv_bfloat16 a0 = __float2bfloat16(f0), a1 = __float2bfloat16(f1);
            __nv_bfloat162 hi; hi.x = a0; hi.y = a1;
            __nv_bfloat162 lo;
            lo.x = __float2bfloat16(f0 - __bfloat162float(a0));
            lo.y = __float2bfloat16(f1 - __bfloat162float(a1));
            *(__nv_bfloat162*)&g_ys[(size_t)(s0 + 8) * DM + col] = hi;
            *(__nv_bfloat162*)&g_ys[N + (size_t)(s0 + 8) * DM + col] = lo;
        }
    }
#undef SWZ
}

// ---------------- launch ----------------------------------------------------
extern "C" void kernel_launch(void* const* d_in, const int* in_sizes, int n_in,
                              void* d_out, int out_size) {
    const float* x     = (const float*)d_in[0];
    const float* q     = (const float*)d_in[1];
    const float* k     = (const float*)d_in[2];
    const float* v     = (const float*)d_in[3];
    const float* o     = (const float*)d_in[4];
    const float* theta = (const float*)d_in[5];
    float* z = (float*)d_out;

    cudaFuncSetAttribute(attn_kernel,
                         cudaFuncAttributeMaxDynamicSharedMemorySize, ATTN_SMEM);
    cudaFuncSetAttribute(gemm0_kernel,
                         cudaFuncAttributeMaxDynamicSharedMemorySize, GSM0_BYTES);
    cudaFuncSetAttribute(gemm1_kernel,
                         cudaFuncAttributeMaxDynamicSharedMemorySize, GSM1_BYTES);

    // attn is the 4th launch -> lands in the ncu-profiled slot
    prep_all_kernel<<<12800, 256>>>(x, q, k, v, o, theta);
    gemm0_kernel<<<dim3(8, 48), 256, GSM0_BYTES>>>();
    prep_attn_kernel<<<(3 * NH * SEQ * 32) / 256, 256>>>();
    attn_kernel<<<dim3(NH, 16), 256, ATTN_SMEM>>>();
    gemm1_kernel<<<dim3(16, 16), 256, GSM1_BYTES>>>(z);
}

// round 16
// speedup vs baseline: 1.0638x; 1.0007x over previous
#include <cuda_runtime.h>
#include <cuda_bf16.h>
#include <math.h>
#include <cstdint>

#define SEQ 2048
#define DM  2048
#define NH  16
#define DQK 128
#define DV  128
#define NCAT 6144   // q|k|v concatenated head-columns

// ---------------- helpers ----------------------------------------------------
__device__ __forceinline__ uint32_t smem_u32(const void* p) {
    uint32_t a;
    asm("{ .reg .u64 t; cvta.to.shared.u64 t, %1; cvt.u32.u64 %0, t; }"
        : "=r"(a) : "l"(p));
    return a;
}

#define CP_ASYNC16(dst, src) \
    asm volatile("cp.async.cg.shared.global [%0], [%1], 16;" :: "r"(dst), "l"(src))
#define CP_COMMIT() asm volatile("cp.async.commit_group;" ::: "memory")
#define CP_WAIT(n)  asm volatile("cp.async.wait_group %0;" :: "n"(n) : "memory")

__device__ __forceinline__ void ldsm4(uint32_t* r, uint32_t addr) {
    asm volatile("ldmatrix.sync.aligned.m8n8.x4.shared.b16 {%0,%1,%2,%3}, [%4];"
                 : "=r"(r[0]), "=r"(r[1]), "=r"(r[2]), "=r"(r[3]) : "r"(addr));
}
__device__ __forceinline__ void ldsm4t(uint32_t* r, uint32_t addr) {
    asm volatile("ldmatrix.sync.aligned.m8n8.x4.trans.shared.b16 {%0,%1,%2,%3}, [%4];"
                 : "=r"(r[0]), "=r"(r[1]), "=r"(r[2]), "=r"(r[3]) : "r"(addr));
}

__device__ __forceinline__ void mma_bf16(float* d, const uint32_t* a,
                                         uint32_t b0, uint32_t b1) {
    asm volatile(
        "mma.sync.aligned.m16n8k16.row.col.f32.bf16.bf16.f32 "
        "{%0,%1,%2,%3}, {%4,%5,%6,%7}, {%8,%9}, {%0,%1,%2,%3};"
        : "+f"(d[0]), "+f"(d[1]), "+f"(d[2]), "+f"(d[3])
        : "r"(a[0]), "r"(a[1]), "r"(a[2]), "r"(a[3]), "r"(b0), "r"(b1));
}

__device__ __forceinline__ uint32_t pack_bf16x2(float lo, float hi) {
    uint32_t d;
    asm("cvt.rn.bf16x2.f32 %0, %1, %2;" : "=r"(d) : "f"(hi), "f"(lo));
    return d;
}

// ---------------- scratch (device globals) ----------------------------------
__device__ __align__(256) __nv_bfloat16 g_xs[2ull * SEQ * DM];
__device__ __align__(256) __nv_bfloat16 g_wt[2ull * NCAT * DM];
__device__ __align__(256) __nv_bfloat16 g_ot[2ull * DM * DM];
__device__ __align__(256) __nv_bfloat16 g_ys[2ull * SEQ * DM];
__device__ __align__(256) __nv_bfloat16 g_qs2[2ull * NH * SEQ * DQK];
__device__ __align__(256) __nv_bfloat16 g_ks2[2ull * NH * SEQ * DQK];
__device__ __align__(256) __nv_bfloat16 g_vs2[2ull * NH * SEQ * DV];
__device__ __align__(256) float g_pqkv[(size_t)SEQ * NCAT];
__device__ float g_sin[SEQ * 64];
__device__ float g_cos[SEQ * 64];

// ---------------- bf16x2 split ----------------------------------------------
__device__ __forceinline__ void split2(float x, __nv_bfloat16& b0, __nv_bfloat16& b1) {
    b0 = __float2bfloat16(x);
    float r = x - __bfloat162float(b0);
    b1 = __float2bfloat16(r);
}

// ---------------- merged prep: rope table | split x | trans w | trans o ------
// blocks: [0,512) rope_table; [512,8704) split_x; [8704,11776) trans_w;
//         [11776,12800) trans_o.  256 threads each.
__global__ void prep_all_kernel(const float* __restrict__ x,
                                const float* __restrict__ q,
                                const float* __restrict__ k,
                                const float* __restrict__ v,
                                const float* __restrict__ o,
                                const float* __restrict__ theta_p) {
    __shared__ float t[64][65];
    int b = blockIdx.x;
    int tid = threadIdx.x;

    if (b < 512) {
        int idx = b * 256 + tid;
        int j = idx & 63;
        int s = idx >> 6;
        float theta = *theta_p;
        float rate = theta * (-(float)j / 64.0f);
        float rot  = (float)s * rate;
        double rd = (double)rot;
        g_sin[idx] = (float)sin(rd);
        g_cos[idx] = (float)cos(rd);
        return;
    }
    if (b < 8704) {
        int i = ((b - 512) * 256 + tid) * 2;
        const size_t N = (size_t)SEQ * DM;
        float2 xv = *(const float2*)&x[i];
        __nv_bfloat16 a0, a1, c0, c1;
        split2(xv.x, a0, a1);
        split2(xv.y, c0, c1);
        __nv_bfloat162 hi; hi.x = a0; hi.y = c0;
        __nv_bfloat162 lo; lo.x = a1; lo.y = c1;
        *(__nv_bfloat162*)&g_xs[i] = hi;
        *(__nv_bfloat162*)&g_xs[N + i] = lo;
        return;
    }
    int tx = tid & 31, ty = tid >> 5;
    if (b < 11776) {
        int bb = b - 8704;
        int bx = bb & 31, by = (bb >> 5) & 1, bz = bb >> 6;
        int which = bz >> 4, h = bz & 15;
        const float* W = (which == 0 ? q : which == 1 ? k : v) + (size_t)h * DM * DQK;
        int kk0 = bx * 64, e0 = by * 64;
        const size_t WS = (size_t)NCAT * DM;
#pragma unroll
        for (int rr = 0; rr < 8; rr++) {
            int row = ty + 8 * rr;
            t[row][tx]      = W[(size_t)(kk0 + row) * DQK + e0 + tx];
            t[row][tx + 32] = W[(size_t)(kk0 + row) * DQK + e0 + tx + 32];
        }
        __syncthreads();
        size_t nbase = (size_t)which * 2048 + h * 128 + e0;
#pragma unroll
        for (int rr = 0; rr < 8; rr++) {
            int n = ty + 8 * rr;
            float v1 = t[2 * tx][n], v2 = t[2 * tx + 1][n];
            __nv_bfloat16 a0, a1, c0, c1;
            split2(v1, a0, a1);
            split2(v2, c0, c1);
            __nv_bfloat162 hi; hi.x = a0; hi.y = c0;
            __nv_bfloat162 lo; lo.x = a1; lo.y = c1;
            size_t oo = (nbase + n) * DM + kk0 + 2 * tx;
            *(__nv_bfloat162*)&g_wt[oo] = hi;
            *(__nv_bfloat162*)&g_wt[WS + oo] = lo;
        }
        return;
    }
    {
        int bb = b - 11776;
        int bx = bb & 31, by = (bb >> 5) & 1, h = bb >> 6;
        const float* O = o + (size_t)h * DV * DM;
        int dm0 = bx * 64, v0 = by * 64;
        const size_t OS = (size_t)DM * DM;
#pragma unroll
        for (int rr = 0; rr < 8; rr++) {
            int row = ty + 8 * rr;
            t[row][tx]      = O[(size_t)(v0 + row) * DM + dm0 + tx];
            t[row][tx + 32] = O[(size_t)(v0 + row) * DM + dm0 + tx + 32];
        }
        __syncthreads();
#pragma unroll
        for (int rr = 0; rr < 8; rr++) {
            int n = ty + 8 * rr;
            float v1 = t[2 * tx][n], v2 = t[2 * tx + 1][n];
            __nv_bfloat16 a0, a1, c0, c1;
            split2(v1, a0, a1);
            split2(v2, c0, c1);
            __nv_bfloat162 hi; hi.x = a0; hi.y = c0;
            __nv_bfloat162 lo; lo.x = a1; lo.y = c1;
            size_t oo = (size_t)(dm0 + n) * DM + h * 128 + v0 + 2 * tx;
            *(__nv_bfloat162*)&g_ot[oo] = hi;
            *(__nv_bfloat162*)&g_ot[OS + oo] = lo;
        }
    }
}

// ---------------- gemm0: R9 config (256x128 tile, BK=64, 2-stage) ------------
#define GSM0_BYTES (2 * 98304)

__global__ void __launch_bounds__(256, 1) gemm0_kernel() {
    extern __shared__ char gsm[];
    const __nv_bfloat16* A3 = g_xs;
    const __nv_bfloat16* B3 = g_wt;
    const size_t As = (size_t)SEQ * DM;
    const size_t Bs = (size_t)NCAT * DM;
    float* C = g_pqkv;
    const int ldc = NCAT;

    uint32_t sb = smem_u32(gsm);
    int tid = threadIdx.x;
    int lane = tid & 31, wid = tid >> 5;
    int wm = wid >> 1, wn = wid & 1;
    int m0 = blockIdx.x * 256, n0 = blockIdx.y * 128;

    float acc[4][8][4];
#pragma unroll
    for (int i = 0; i < 4; i++)
#pragma unroll
        for (int j = 0; j < 8; j++)
#pragma unroll
            for (int r = 0; r < 4; r++) acc[i][j][r] = 0.0f;

    auto load_stage = [&](int s, int kc) {
        int k0 = kc * 64;
#pragma unroll
        for (int p = 0; p < 2; p++) {
            const __nv_bfloat16* gp = A3 + p * As + (size_t)m0 * DM + k0;
            uint32_t base = sb + s * 98304 + p * 32768;
#pragma unroll
            for (int i = 0; i < 8; i++) {
                int idx = i * 256 + tid;
                int row = idx >> 3, c = idx & 7;
                uint32_t dst = base + row * 128 + ((c ^ (row & 7)) << 4);
                CP_ASYNC16(dst, gp + (size_t)row * DM + c * 8);
            }
        }
#pragma unroll
        for (int p = 0; p < 2; p++) {
            const __nv_bfloat16* gp = B3 + p * Bs + (size_t)n0 * DM + k0;
            uint32_t base = sb + s * 98304 + 65536 + p * 16384;
#pragma unroll
            for (int i = 0; i < 4; i++) {
                int idx = i * 256 + tid;
                int row = idx >> 3, c = idx & 7;
                uint32_t dst = base + row * 128 + ((c ^ (row & 7)) << 4);
                CP_ASYNC16(dst, gp + (size_t)row * DM + c * 8);
            }
        }
    };

    load_stage(0, 0); CP_COMMIT();

    for (int kc = 0; kc < 32; kc++) {
        int s = kc & 1;
        if (kc + 1 < 32) { load_stage(s ^ 1, kc + 1); CP_COMMIT(); CP_WAIT(1); }
        else            { CP_WAIT(0); }
        __syncthreads();

        uint32_t stage = sb + s * 98304;
#pragma unroll
        for (int ks = 0; ks < 4; ks++) {
            uint32_t a[2][4][4];
#pragma unroll
            for (int p = 0; p < 2; p++)
#pragma unroll
                for (int mf = 0; mf < 4; mf++) {
                    int row = wm * 64 + mf * 16 + (lane & 15);
                    int c = ks * 2 + ((lane >> 4) & 1);
                    uint32_t addr = stage + p * 32768 + row * 128 +
                                    ((c ^ (row & 7)) << 4);
                    ldsm4(a[p][mf], addr);
                }
            uint32_t b[2][4][4];
#pragma unroll
            for (int p = 0; p < 2; p++)
#pragma unroll
                for (int nf2 = 0; nf2 < 4; nf2++) {
                    int row = wn * 64 + nf2 * 16 + (lane & 7) + ((lane >> 4) & 1) * 8;
                    int c = ks * 2 + ((lane >> 3) & 1);
                    uint32_t addr = stage + 65536 + p * 16384 + row * 128 +
                                    ((c ^ (row & 7)) << 4);
                    ldsm4(b[p][nf2], addr);
                }
#pragma unroll
            for (int mf = 0; mf < 4; mf++)
#pragma unroll
                for (int nf2 = 0; nf2 < 4; nf2++) {
                    mma_bf16(acc[mf][2 * nf2 + 0], a[0][mf], b[0][nf2][0], b[0][nf2][1]);
                    mma_bf16(acc[mf][2 * nf2 + 1], a[0][mf], b[0][nf2][2], b[0][nf2][3]);
                    mma_bf16(acc[mf][2 * nf2 + 0], a[0][mf], b[1][nf2][0], b[1][nf2][1]);
                    mma_bf16(acc[mf][2 * nf2 + 1], a[0][mf], b[1][nf2][2], b[1][nf2][3]);
                    mma_bf16(acc[mf][2 * nf2 + 0], a[1][mf], b[0][nf2][0], b[0][nf2][1]);
                    mma_bf16(acc[mf][2 * nf2 + 1], a[1][mf], b[0][nf2][2], b[0][nf2][3]);
                }
        }
        __syncthreads();
    }

#pragma unroll
    for (int mf = 0; mf < 4; mf++) {
        int r0 = m0 + wm * 64 + mf * 16 + (lane >> 2);
#pragma unroll
        for (int nf = 0; nf < 8; nf++) {
            int cb = n0 + wn * 64 + nf * 8 + (lane & 3) * 2;
            float2 v01 = make_float2(acc[mf][nf][0], acc[mf][nf][1]);
            float2 v23 = make_float2(acc[mf][nf][2], acc[mf][nf][3]);
            *(float2*)&C[(size_t)r0 * ldc + cb] = v01;
            *(float2*)&C[(size_t)(r0 + 8) * ldc + cb] = v23;
        }
    }
}

// ---------------- gemm1: R14 config (128x128 tile, BK=32, 2 CTAs/SM) ---------
#define GSM1_BYTES 65536
#define NKC 64

__global__ void __launch_bounds__(256, 2) gemm1_kernel(float* Cout) {
    extern __shared__ char gsm[];
    const __nv_bfloat16* A3 = g_ys;
    const __nv_bfloat16* B3 = g_ot;
    const size_t As = (size_t)SEQ * DM;
    const size_t Bs = (size_t)DM * DM;

    uint32_t sb = smem_u32(gsm);
    int tid = threadIdx.x;
    int lane = tid & 31, wid = tid >> 5;
    int wm = wid >> 2, wn = wid & 3;
    int m0 = blockIdx.x * 128, n0 = blockIdx.y * 128;

    float acc[4][4][4];
#pragma unroll
    for (int i = 0; i < 4; i++)
#pragma unroll
        for (int j = 0; j < 4; j++)
#pragma unroll
            for (int r = 0; r < 4; r++) acc[i][j][r] = 0.0f;

    auto load_stage = [&](int st, int kc) {
        int k0 = kc * 32;
        uint32_t base = sb + st * 32768;
#pragma unroll
        for (int i = 0; i < 4; i++) {
            int idx = i * 256 + tid;
            int row = idx >> 3, ch = idx & 7;
            int p = ch >> 2, c = ch & 3;
            uint32_t dst = base + row * 128 + ((ch ^ (row & 7)) << 4);
            CP_ASYNC16(dst, A3 + p * As + (size_t)(m0 + row) * DM + k0 + c * 8);
        }
#pragma unroll
        for (int i = 0; i < 4; i++) {
            int idx = i * 256 + tid;
            int row = idx >> 3, ch = idx & 7;
            int p = ch >> 2, c = ch & 3;
            uint32_t dst = base + 16384 + row * 128 + ((ch ^ (row & 7)) << 4);
            CP_ASYNC16(dst, B3 + p * Bs + (size_t)(n0 + row) * DM + k0 + c * 8);
        }
    };

    load_stage(0, 0); CP_COMMIT();

    for (int kc = 0; kc < NKC; kc++) {
        int st = kc & 1;
        if (kc + 1 < NKC) { load_stage(st ^ 1, kc + 1); CP_COMMIT(); CP_WAIT(1); }
        else              { CP_WAIT(0); }
        __syncthreads();

        uint32_t stage = sb + st * 32768;
        uint32_t stageB = stage + 16384;
#pragma unroll
        for (int ks = 0; ks < 2; ks++) {
            uint32_t b0[2][4], b1[2][4];
#pragma unroll
            for (int nf2 = 0; nf2 < 2; nf2++) {
                int r = wn * 32 + nf2 * 16 + (lane & 7) + ((lane >> 4) & 1) * 8;
                int ci0 = (0 + ks * 2 + ((lane >> 3) & 1)) ^ (r & 7);
                int ci1 = (4 + ks * 2 + ((lane >> 3) & 1)) ^ (r & 7);
                ldsm4(b0[nf2], stageB + r * 128 + (ci0 << 4));
                ldsm4(b1[nf2], stageB + r * 128 + (ci1 << 4));
            }
            uint32_t a0[4][4];
#pragma unroll
            for (int mf = 0; mf < 4; mf++) {
                int r = wm * 64 + mf * 16 + (lane & 15);
                int ci = (0 + ks * 2 + (lane >> 4)) ^ (r & 7);
                ldsm4(a0[mf], stage + r * 128 + (ci << 4));
            }
#pragma unroll
            for (int mf = 0; mf < 4; mf++)
#pragma unroll
                for (int nf2 = 0; nf2 < 2; nf2++) {
                    mma_bf16(acc[mf][2 * nf2 + 0], a0[mf], b0[nf2][0], b0[nf2][1]);
                    mma_bf16(acc[mf][2 * nf2 + 1], a0[mf], b0[nf2][2], b0[nf2][3]);
                    mma_bf16(acc[mf][2 * nf2 + 0], a0[mf], b1[nf2][0], b1[nf2][1]);
                    mma_bf16(acc[mf][2 * nf2 + 1], a0[mf], b1[nf2][2], b1[nf2][3]);
                }
            uint32_t a1[4][4];
#pragma unroll
            for (int mf = 0; mf < 4; mf++) {
                int r = wm * 64 + mf * 16 + (lane & 15);
                int ci = (4 + ks * 2 + (lane >> 4)) ^ (r & 7);
                ldsm4(a1[mf], stage + r * 128 + (ci << 4));
            }
#pragma unroll
            for (int mf = 0; mf < 4; mf++)
#pragma unroll
                for (int nf2 = 0; nf2 < 2; nf2++) {
                    mma_bf16(acc[mf][2 * nf2 + 0], a1[mf], b0[nf2][0], b0[nf2][1]);
                    mma_bf16(acc[mf][2 * nf2 + 1], a1[mf], b0[nf2][2], b0[nf2][3]);
                }
        }
        __syncthreads();
    }

    const float alpha = 1.0f / 2048.0f;
#pragma unroll
    for (int mf = 0; mf < 4; mf++) {
        int r0 = m0 + wm * 64 + mf * 16 + (lane >> 2);
#pragma unroll
        for (int nf = 0; nf < 4; nf++) {
            int cb = n0 + wn * 32 + nf * 8 + (lane & 3) * 2;
            float2 v01 = make_float2(acc[mf][nf][0] * alpha, acc[mf][nf][1] * alpha);
            float2 v23 = make_float2(acc[mf][nf][2] * alpha, acc[mf][nf][3] * alpha);
            *(float2*)&Cout[(size_t)r0 * DM + cb] = v01;
            *(float2*)&Cout[(size_t)(r0 + 8) * DM + cb] = v23;
        }
    }
}

// ---------------- prep attn: RoPE + bf16x2 split of q,k,v --------------------
__global__ void prep_attn_kernel() {
    int g = blockIdx.x * blockDim.x + threadIdx.x;
    int jp = g & 31;
    int s = (g >> 5) & (SEQ - 1);
    int h = (g >> 16) & (NH - 1);
    int t = g >> 20;                                  // 0=q, 1=k, 2=v
    const float* row = g_pqkv + (size_t)s * NCAT + t * 2048 + h * 128;
    size_t obase = ((size_t)h * SEQ + s) * 128;
    const size_t HSD = (size_t)NH * SEQ * 128;
    int j0 = 2 * jp;
    __nv_bfloat16 a0, a1, c0, c1;
    if (t < 2) {
        float2 x1 = *(const float2*)&row[j0];
        float2 x2 = *(const float2*)&row[j0 + 64];
        float2 sn = *(const float2*)&g_sin[s * 64 + j0];
        float2 cs = *(const float2*)&g_cos[s * 64 + j0];
        const float dq4 = 3.3635856610148585f;
        float r1a = (cs.x * x1.x - sn.x * x2.x) / dq4;
        float r1b = (cs.y * x1.y - sn.y * x2.y) / dq4;
        float r2a = (sn.x * x1.x + cs.x * x2.x) / dq4;
        float r2b = (sn.y * x1.y + cs.y * x2.y) / dq4;
        __nv_bfloat16* dst = (t == 0 ? g_qs2 : g_ks2);
        split2(r1a, a0, a1); split2(r1b, c0, c1);
        { __nv_bfloat162 hi; hi.x = a0; hi.y = c0;
          __nv_bfloat162 lo; lo.x = a1; lo.y = c1;
          *(__nv_bfloat162*)&dst[obase + j0] = hi;
          *(__nv_bfloat162*)&dst[HSD + obase + j0] = lo; }
        split2(r2a, a0, a1); split2(r2b, c0, c1);
        { __nv_bfloat162 hi; hi.x = a0; hi.y = c0;
          __nv_bfloat162 lo; lo.x = a1; lo.y = c1;
          *(__nv_bfloat162*)&dst[obase + j0 + 64] = hi;
          *(__nv_bfloat162*)&dst[HSD + obase + j0 + 64] = lo; }
    } else {
        float2 v1 = *(const float2*)&row[j0];
        float2 v2 = *(const float2*)&row[j0 + 64];
        split2(v1.x, a0, a1); split2(v1.y, c0, c1);
        { __nv_bfloat162 hi; hi.x = a0; hi.y = c0;
          __nv_bfloat162 lo; lo.x = a1; lo.y = c1;
          *(__nv_bfloat162*)&g_vs2[obase + j0] = hi;
          *(__nv_bfloat162*)&g_vs2[HSD + obase + j0] = lo; }
        split2(v2.x, a0, a1); split2(v2.y, c0, c1);
        { __nv_bfloat162 hi; hi.x = a0; hi.y = c0;
          __nv_bfloat162 lo; lo.x = a1; lo.y = c1;
          *(__nv_bfloat162*)&g_vs2[obase + j0 + 64] = hi;
          *(__nv_bfloat162*)&g_vs2[HSD + obase + j0 + 64] = lo; }
    }
}

// ---------------- flash attention (bf16x2 mma.sync) --------------------------
#define ATTN_SMEM 196608

__global__ void __launch_bounds__(256, 1) attn_kernel() {
    extern __shared__ char asmem[];
    uint32_t sb = smem_u32(asmem);
    int tid = threadIdx.x, lane = tid & 31, wq = tid >> 5;
    int h = blockIdx.x;
    int qt = 15 - (int)blockIdx.y;    // LPT: heavy q-tiles first
    int q0 = qt * 128;
    const size_t HSD = (size_t)NH * SEQ * 128;

    const __nv_bfloat16* Qg = g_qs2 + ((size_t)h * SEQ + q0) * 128;
    const __nv_bfloat16* Kg = g_ks2 + (size_t)h * SEQ * 128;
    const __nv_bfloat16* Vg = g_vs2 + (size_t)h * SEQ * 128;

    const uint32_t Qb = sb;
    const uint32_t St0 = sb + 65536, St1 = sb + 131072;

#define SWZ(base, row, c) ((base) + (row) * 256 + ((((c) ^ (((row) & 7) << 1)) & 15) << 4))

#pragma unroll
    for (int i = 0; i < 16; i++) {
        int idx = i * 256 + tid;
        int p = idx >> 11, rem = idx & 2047, row = rem >> 4, c = rem & 15;
        CP_ASYNC16(SWZ(Qb + p * 32768, row, c),
                   (const char*)(Qg + p * HSD) + row * 256 + c * 16);
    }
    int nkt = 2 * qt + 2;

    auto loadKV = [&](uint32_t stage, int kt) {
        int kb = kt * 64;
#pragma unroll
        for (int i = 0; i < 16; i++) {
            int idx = i * 256 + tid;
            int tile = idx >> 11;
            int p = (idx >> 10) & 1, row = (idx >> 4) & 63, c = idx & 15;
            const __nv_bfloat16* src =
                (tile ? Vg : Kg) + p * HSD + (size_t)(kb + row) * 128;
            CP_ASYNC16(SWZ(stage + tile * 32768 + p * 16384, row, c),
                       (const char*)src + c * 16);
        }
    };
    loadKV(St0, 0); CP_COMMIT();
    loadKV(St1, 1); CP_COMMIT();

    float y[16][4];
#pragma unroll
    for (int i = 0; i < 16; i++)
#pragma unroll
        for (int r = 0; r < 4; r++) y[i][r] = 0.0f;
    float mr0 = -INFINITY, mr1 = -INFINITY, l0 = 0.0f, l1 = 0.0f;
    int qrow0 = q0 + wq * 16 + (lane >> 2);

    for (int kt = 0; kt < nkt; kt++) {
        CP_WAIT(1);
        __syncthreads();
        uint32_t S = (kt & 1) ? St1 : St0;
        int kbase = kt * 64;

        float sacc[8][4];
#pragma unroll
        for (int i = 0; i < 8; i++)
#pragma unroll
            for (int r = 0; r < 4; r++) sacc[i][r] = 0.0f;

#pragma unroll
        for (int kf = 0; kf < 8; kf++) {
            uint32_t aq0[4], aq1[4];
            {
                int row = wq * 16 + (lane & 15);
                int c = kf * 2 + (lane >> 4);
                ldsm4(aq0, SWZ(Qb, row, c));
                ldsm4(aq1, SWZ(Qb + 32768, row, c));
            }
#pragma unroll
            for (int ng = 0; ng < 4; ng++) {
                uint32_t kb0[4], kb1[4];
                int row = ng * 16 + (lane & 7) + ((lane >> 4) & 1) * 8;
                int c = kf * 2 + ((lane >> 3) & 1);
                ldsm4(kb0, SWZ(S, row, c));
                ldsm4(kb1, SWZ(S + 16384, row, c));
                mma_bf16(sacc[2 * ng + 0], aq0, kb0[0], kb0[1]);
                mma_bf16(sacc[2 * ng + 1], aq0, kb0[2], kb0[3]);
                mma_bf16(sacc[2 * ng + 0], aq0, kb1[0], kb1[1]);
                mma_bf16(sacc[2 * ng + 1], aq0, kb1[2], kb1[3]);
                mma_bf16(sacc[2 * ng + 0], aq1, kb0[0], kb0[1]);
                mma_bf16(sacc[2 * ng + 1], aq1, kb0[2], kb0[3]);
            }
        }

        if (kbase + 64 > q0 + wq * 16) {
#pragma unroll
            for (int nf = 0; nf < 8; nf++) {
                int col = kbase + nf * 8 + (lane & 3) * 2;
                if (col > qrow0)         sacc[nf][0] -= 1.0e9f;
                if (col + 1 > qrow0)     sacc[nf][1] -= 1.0e9f;
                if (col > qrow0 + 8)     sacc[nf][2] -= 1.0e9f;
                if (col + 1 > qrow0 + 8) sacc[nf][3] -= 1.0e9f;
            }
        }

        float mx0 = -INFINITY, mx1 = -INFINITY;
#pragma unroll
        for (int nf = 0; nf < 8; nf++) {
            mx0 = fmaxf(mx0, fmaxf(sacc[nf][0], sacc[nf][1]));
            mx1 = fmaxf(mx1, fmaxf(sacc[nf][2], sacc[nf][3]));
        }
        mx0 = fmaxf(mx0, __shfl_xor_sync(0xffffffffu, mx0, 1));
        mx0 = fmaxf(mx0, __shfl_xor_sync(0xffffffffu, mx0, 2));
        mx1 = fmaxf(mx1, __shfl_xor_sync(0xffffffffu, mx1, 1));
        mx1 = fmaxf(mx1, __shfl_xor_sync(0xffffffffu, mx1, 2));
        float mn0 = fmaxf(mr0, mx0), mn1 = fmaxf(mr1, mx1);
        float c0 = __expf(mr0 - mn0), c1 = __expf(mr1 - mn1);
        float ls0 = 0.0f, ls1 = 0.0f;
#pragma unroll
        for (int nf = 0; nf < 8; nf++) {
            sacc[nf][0] = __expf(sacc[nf][0] - mn0);
            sacc[nf][1] = __expf(sacc[nf][1] - mn0);
            sacc[nf][2] = __expf(sacc[nf][2] - mn1);
            sacc[nf][3] = __expf(sacc[nf][3] - mn1);
            ls0 += sacc[nf][0] + sacc[nf][1];
            ls1 += sacc[nf][2] + sacc[nf][3];
        }
        ls0 += __shfl_xor_sync(0xffffffffu, ls0, 1);
        ls0 += __shfl_xor_sync(0xffffffffu, ls0, 2);
        ls1 += __shfl_xor_sync(0xffffffffu, ls1, 1);
        ls1 += __shfl_xor_sync(0xffffffffu, ls1, 2);
        l0 = l0 * c0 + ls0; l1 = l1 * c1 + ls1;
        mr0 = mn0; mr1 = mn1;
#pragma unroll
        for (int i = 0; i < 16; i++) {
            y[i][0] *= c0; y[i][1] *= c0; y[i][2] *= c1; y[i][3] *= c1;
        }

#pragma unroll
        for (int kf2 = 0; kf2 < 4; kf2++) {
            uint32_t p0[4], p1[4];
#pragma unroll
            for (int half = 0; half < 2; half++) {
                float f0 = sacc[2 * kf2 + half][0], f1 = sacc[2 * kf2 + half][1];
                float f2 = sacc[2 * kf2 + half][2], f3 = sacc[2 * kf2 + half][3];
                float g0 = f0 - __bfloat162float(__float2bfloat16(f0));
                float g1 = f1 - __bfloat162float(__float2bfloat16(f1));
                float g2 = f2 - __bfloat162float(__float2bfloat16(f2));
                float g3 = f3 - __bfloat162float(__float2bfloat16(f3));
                p0[2 * half + 0] = pack_bf16x2(f0, f1);
                p0[2 * half + 1] = pack_bf16x2(f2, f3);
                p1[2 * half + 0] = pack_bf16x2(g0, g1);
                p1[2 * half + 1] = pack_bf16x2(g2, g3);
            }
            uint32_t a0[4] = {p0[0], p0[1], p0[2], p0[3]};
            uint32_t a1[4] = {p1[0], p1[1], p1[2], p1[3]};
#pragma unroll
            for (int ng = 0; ng < 8; ng++) {
                uint32_t vb0[4], vb1[4];
                int row = kf2 * 16 + (lane & 15);
                int c = ng * 2 + (lane >> 4);
                ldsm4t(vb0, SWZ(S + 32768, row, c));
                ldsm4t(vb1, SWZ(S + 49152, row, c));
                mma_bf16(y[2 * ng + 0], a0, vb0[0], vb0[1]);
                mma_bf16(y[2 * ng + 1], a0, vb0[2], vb0[3]);
                mma_bf16(y[2 * ng + 0], a0, vb1[0], vb1[1]);
                mma_bf16(y[2 * ng + 1], a0, vb1[2], vb1[3]);
                mma_bf16(y[2 * ng + 0], a1, vb0[0], vb0[1]);
                mma_bf16(y[2 * ng + 1], a1, vb0[2], vb0[3]);
            }
        }

        __syncthreads();
        if (kt + 2 < nkt) loadKV((kt & 1) ? St1 : St0, kt + 2);
        CP_COMMIT();
    }

    float inv0 = 1.0f / l0, inv1 = 1.0f / l1;
    int s0 = q0 + wq * 16 + (lane >> 2);
    const size_t N = (size_t)SEQ * DM;
#pragma unroll
    for (int nf = 0; nf < 16; nf++) {
        int col = h * 128 + nf * 8 + (lane & 3) * 2;
        {
            float f0 = y[nf][0] * inv0, f1 = y[nf][1] * inv0;
            __nv_bfloat16 a0 = __float2bfloat16(f0), a1 = __float2bfloat16(f1);
            __nv_bfloat162 hi; hi.x = a0; hi.y = a1;
            __nv_bfloat162 lo;
            lo.x = __float2bfloat16(f0 - __bfloat162float(a0));
            lo.y = __float2bfloat16(f1 - __bfloat162float(a1));
            *(__nv_bfloat162*)&g_ys[(size_t)s0 * DM + col] = hi;
            *(__nv_bfloat162*)&g_ys[N + (size_t)s0 * DM + col] = lo;
        }
        {
            float f0 = y[nf][2] * inv1, f1 = y[nf][3] * inv1;
            __nv_bfloat16 a0 = __float2bfloat16(f0), a1 = __float2bfloat16(f1);
            __nv_bfloat162 hi; hi.x = a0; hi.y = a1;
            __nv_bfloat162 lo;
            lo.x = __float2bfloat16(f0 - __bfloat162float(a0));
            lo.y = __float2bfloat16(f1 - __bfloat162float(a1));
            *(__nv_bfloat162*)&g_ys[(size_t)(s0 + 8) * DM + col] = hi;
            *(__nv_bfloat162*)&g_ys[N + (size_t)(s0 + 8) * DM + col] = lo;
        }
    }
#undef SWZ
}

// ---------------- launch ----------------------------------------------------
extern "C" void kernel_launch(void* const* d_in, const int* in_sizes, int n_in,
                              void* d_out, int out_size) {
    const float* x     = (const float*)d_in[0];
    const float* q     = (const float*)d_in[1];
    const float* k     = (const float*)d_in[2];
    const float* v     = (const float*)d_in[3];
    const float* o     = (const float*)d_in[4];
    const float* theta = (const float*)d_in[5];
    float* z = (float*)d_out;

    cudaFuncSetAttribute(attn_kernel,
                         cudaFuncAttributeMaxDynamicSharedMemorySize, ATTN_SMEM);
    cudaFuncSetAttribute(gemm0_kernel,
                         cudaFuncAttributeMaxDynamicSharedMemorySize, GSM0_BYTES);
    cudaFuncSetAttribute(gemm1_kernel,
                         cudaFuncAttributeMaxDynamicSharedMemorySize, GSM1_BYTES);

    // attn is the 4th launch -> lands in the ncu-profiled slot
    prep_all_kernel<<<12800, 256>>>(x, q, k, v, o, theta);
    gemm0_kernel<<<dim3(8, 48), 256, GSM0_BYTES>>>();
    prep_attn_kernel<<<(3 * NH * SEQ * 32) / 256, 256>>>();
    attn_kernel<<<dim3(NH, 16), 256, ATTN_SMEM>>>();
    gemm1_kernel<<<dim3(16, 16), 256, GSM1_BYTES>>>(z);
}